// round 1
// baseline (speedup 1.0000x reference)
#include <cuda_runtime.h>
#include <math.h>

#define N_NODES 100000
#define N_EDGES 1000000
#define DM 64            // model dim (= H*D)
#define NEG_BIG (-3.4028235e38f)

// ---------------- scratch (device globals: allocation-free) ----------------
__device__ float g_qk[(size_t)N_NODES * DM];
__device__ float g_v[(size_t)N_NODES * DM];
__device__ float g_ctx[(size_t)N_NODES * DM];
__device__ int   g_off[N_NODES + 1];
__device__ float g_attn_fb[(size_t)N_EDGES * 4];
__device__ float g_out_fb[(size_t)N_NODES * DM];

// ---------------- f32x2 packed-FMA helpers (sm_100+) ----------------
__device__ __forceinline__ unsigned long long pack2(float lo, float hi) {
    unsigned long long r;
    asm("mov.b64 %0, {%1,%2};" : "=l"(r) : "f"(lo), "f"(hi));
    return r;
}
__device__ __forceinline__ void unpack2(unsigned long long p, float& lo, float& hi) {
    asm("mov.b64 {%0,%1}, %2;" : "=f"(lo), "=f"(hi) : "l"(p));
}
__device__ __forceinline__ void ffma2(unsigned long long& c, unsigned long long a, unsigned long long b) {
    asm("fma.rn.f32x2 %0, %1, %2, %0;" : "+l"(c) : "l"(a), "l"(b));
}

// ---------------- GEMM: C[M x 64] = A[M x 64] @ W[64 x 64] + b ----------------
// Block tile 128x64, BK=32, 256 threads (tx 0..15 -> 4 cols, ty 0..15 -> 8 rows).
// A staged transposed in smem (As[k][m]) so row-pairs load as float2; packed
// f32x2 FMA for 2x fp32 throughput.
#define BM 128
#define BN 64
#define BK 32

__global__ __launch_bounds__(256) void gemm_n64_kernel(
    const float* __restrict__ A, const float* __restrict__ W,
    const float* __restrict__ bias, float* __restrict__ C, int M)
{
    __shared__ float As[BK][BM + 4];   // [k][m], row stride 132 floats (16B-mult)
    __shared__ float Ws[BK][BN + 4];   // [k][c], row stride 68 floats (16B-mult)

    const int tid = threadIdx.x;
    const int tx = tid & 15;           // column group: cols tx*4 .. tx*4+3
    const int ty = tid >> 4;           // row group:    rows ty*8 .. ty*8+7
    const int bm = blockIdx.x * BM;

    // acc2[ip][j] packs rows (2ip, 2ip+1) of column (tx*4 + j)
    unsigned long long acc2[4][4];
#pragma unroll
    for (int i = 0; i < 4; i++)
#pragma unroll
        for (int j = 0; j < 4; j++) acc2[i][j] = pack2(0.f, 0.f);

    for (int kk = 0; kk < DM; kk += BK) {
        // --- load A tile: 128 rows x 32 k, transposed into As[k][m] ---
#pragma unroll
        for (int i = 0; i < 4; i++) {
            int idx = tid + i * 256;       // 0..1023 float4 slots
            int r = idx >> 3;              // 0..127
            int c4 = idx & 7;              // 0..7 (float4 within 32 k)
            float4 v = make_float4(0.f, 0.f, 0.f, 0.f);
            if (bm + r < M)
                v = reinterpret_cast<const float4*>(A + (size_t)(bm + r) * DM + kk)[c4];
            As[c4 * 4 + 0][r] = v.x;
            As[c4 * 4 + 1][r] = v.y;
            As[c4 * 4 + 2][r] = v.z;
            As[c4 * 4 + 3][r] = v.w;
        }
        // --- load W tile: 32 k x 64 cols ---
#pragma unroll
        for (int i = 0; i < 2; i++) {
            int idx = tid + i * 256;       // 0..511 float4 slots
            int kr = idx >> 4;             // 0..31
            int c4 = idx & 15;             // 0..15
            float4 v = reinterpret_cast<const float4*>(W + (size_t)(kk + kr) * DM)[c4];
            *reinterpret_cast<float4*>(&Ws[kr][c4 * 4]) = v;
        }
        __syncthreads();

#pragma unroll
        for (int k = 0; k < BK; k++) {
            float4 w = *reinterpret_cast<const float4*>(&Ws[k][tx * 4]);
            unsigned long long wd[4];
            wd[0] = pack2(w.x, w.x);
            wd[1] = pack2(w.y, w.y);
            wd[2] = pack2(w.z, w.z);
            wd[3] = pack2(w.w, w.w);
            unsigned long long ap[4];
#pragma unroll
            for (int i = 0; i < 4; i++) {
                float2 a = *reinterpret_cast<const float2*>(&As[k][ty * 8 + 2 * i]);
                ap[i] = pack2(a.x, a.y);
            }
#pragma unroll
            for (int i = 0; i < 4; i++)
#pragma unroll
                for (int j = 0; j < 4; j++) ffma2(acc2[i][j], ap[i], wd[j]);
        }
        __syncthreads();
    }

    // --- epilogue: add bias, store ---
    float4 bv = *reinterpret_cast<const float4*>(bias + tx * 4);
#pragma unroll
    for (int i = 0; i < 4; i++) {
        float lo[4], hi[4];
#pragma unroll
        for (int j = 0; j < 4; j++) unpack2(acc2[i][j], lo[j], hi[j]);
        int r0 = bm + ty * 8 + 2 * i;
        if (r0 < M) {
            float4 o = make_float4(lo[0] + bv.x, lo[1] + bv.y, lo[2] + bv.z, lo[3] + bv.w);
            *reinterpret_cast<float4*>(C + (size_t)r0 * DM + tx * 4) = o;
        }
        if (r0 + 1 < M) {
            float4 o = make_float4(hi[0] + bv.x, hi[1] + bv.y, hi[2] + bv.z, hi[3] + bv.w);
            *reinterpret_cast<float4*>(C + (size_t)(r0 + 1) * DM + tx * 4) = o;
        }
    }
}

// ---------------- segment offsets: binary search over sorted receivers ----------------
__global__ void offsets_kernel(const int* __restrict__ recv) {
    int n = blockIdx.x * blockDim.x + threadIdx.x;
    if (n > N_NODES) return;
    int lo = 0, hi = N_EDGES;
    while (lo < hi) {
        int mid = (lo + hi) >> 1;
        if (recv[mid] < n) lo = mid + 1; else hi = mid;
    }
    g_off[n] = lo;
}

// ---------------- edge kernel: scores + segment softmax + weighted scatter ----------------
// One warp per receiver node. Lane layout: lane = edge_slot*4 + head
// (8 edges x 4 heads per chunk). Online softmax across chunks; raw scores
// staged in the attn buffer (each lane re-reads only its own writes).
__global__ __launch_bounds__(256) void edge_attn_kernel(
    const int* __restrict__ senders, float* __restrict__ attn)
{
    const int warp = threadIdx.x >> 5;
    const int lane = threadIdx.x & 31;
    const int n = blockIdx.x * 8 + warp;
    if (n >= N_NODES) return;

    const int beg = g_off[n];
    const int end = g_off[n + 1];

    float acc0 = 0.f, acc1 = 0.f;      // ctx dims: lane, lane+32

    if (beg < end) {
        const int h = lane & 3;        // head
        const int eo = lane >> 2;      // edge slot within chunk (0..7)

        // q slice for this lane's head: 16 floats = 4 float4
        const float4* qp = reinterpret_cast<const float4*>(g_qk + (size_t)n * DM) + h * 4;
        const float4 q0 = qp[0], q1 = qp[1], q2 = qp[2], q3 = qp[3];

        float m = NEG_BIG, z = 0.f;

        // ---- pass 1: scores, online max/sum ----
        for (int base = beg; base < end; base += 8) {
            int e = base + eo;
            bool act = (e < end);
            float sc = NEG_BIG;
            if (act) {
                int s = senders[e];
                const float4* kp = reinterpret_cast<const float4*>(g_qk + (size_t)s * DM) + h * 4;
                float4 k0 = kp[0], k1 = kp[1], k2 = kp[2], k3 = kp[3];
                sc = q0.x * k0.x + q0.y * k0.y + q0.z * k0.z + q0.w * k0.w
                   + q1.x * k1.x + q1.y * k1.y + q1.z * k1.z + q1.w * k1.w
                   + q2.x * k2.x + q2.y * k2.y + q2.z * k2.z + q2.w * k2.w
                   + q3.x * k3.x + q3.y * k3.y + q3.z * k3.z + q3.w * k3.w;
                attn[(size_t)base * 4 + lane] = sc;   // stage raw score
            }
            float cm = sc;
#pragma unroll
            for (int o = 4; o < 32; o <<= 1)
                cm = fmaxf(cm, __shfl_xor_sync(0xffffffffu, cm, o));
            float nm = fmaxf(m, cm);
            float ex = act ? expf(sc - nm) : 0.f;
#pragma unroll
            for (int o = 4; o < 32; o <<= 1)
                ex += __shfl_xor_sync(0xffffffffu, ex, o);
            z = z * expf(m - nm) + ex;
            m = nm;
        }
        float inv = 1.0f / z;

        // ---- pass 2: normalize, write attn, weighted v scatter ----
        const int hi0 = lane >> 4;     // which head drives dim=lane (0/1); dim=lane+32 is head 2/3
        for (int base = beg; base < end; base += 8) {
            int e = base + eo;
            bool act = (e < end);
            float a = 0.f;
            int s = 0;
            if (act) {
                float sc = attn[(size_t)base * 4 + lane];
                a = expf(sc - m) * inv;
                attn[(size_t)base * 4 + lane] = a;    // final attention weight
                s = senders[e];
            }
            int cnt = min(8, end - base);
            for (int j = 0; j < cnt; j++) {
                int sj = __shfl_sync(0xffffffffu, s, j * 4);
                float a0 = __shfl_sync(0xffffffffu, a, j * 4 + hi0);
                float a1 = __shfl_sync(0xffffffffu, a, j * 4 + 2 + hi0);
                const float* vp = g_v + (size_t)sj * DM;
                acc0 += a0 * vp[lane];
                acc1 += a1 * vp[lane + 32];
            }
        }
    }

    g_ctx[(size_t)n * DM + lane] = acc0;
    g_ctx[(size_t)n * DM + lane + 32] = acc1;
}

// ---------------- launch ----------------
extern "C" void kernel_launch(void* const* d_in, const int* in_sizes, int n_in,
                              void* d_out, int out_size)
{
    const float* nodes   = (const float*)d_in[0];
    const float* W_qk    = (const float*)d_in[1];
    const float* b_qk    = (const float*)d_in[2];
    const float* W_v     = (const float*)d_in[3];
    const float* b_v     = (const float*)d_in[4];
    const float* W_out   = (const float*)d_in[5];
    const float* b_out   = (const float*)d_in[6];
    const int*   senders = (const int*)d_in[7];
    const int*   recv    = (const int*)d_in[8];

    float *qk_p = nullptr, *v_p = nullptr, *ctx_p = nullptr, *attn_fb = nullptr, *out_fb = nullptr;
    cudaGetSymbolAddress((void**)&qk_p,   g_qk);
    cudaGetSymbolAddress((void**)&v_p,    g_v);
    cudaGetSymbolAddress((void**)&ctx_p,  g_ctx);
    cudaGetSymbolAddress((void**)&attn_fb, g_attn_fb);
    cudaGetSymbolAddress((void**)&out_fb,  g_out_fb);

    const long long OUT_E  = (long long)N_NODES * DM;   // 6,400,000
    const long long ATTN_E = (long long)N_EDGES * 4;    // 4,000,000

    float* out_ptr;
    float* attn_ptr;
    if ((long long)out_size >= OUT_E + ATTN_E) {        // tuple (out, attn) flattened
        out_ptr  = (float*)d_out;
        attn_ptr = (float*)d_out + OUT_E;
    } else if ((long long)out_size == ATTN_E) {         // attn only
        attn_ptr = (float*)d_out;
        out_ptr  = out_fb;
    } else {                                            // out only (or unknown)
        out_ptr  = (float*)d_out;
        attn_ptr = attn_fb;
    }

    const int gemm_grid = (N_NODES + BM - 1) / BM;

    offsets_kernel<<<(N_NODES + 1 + 255) / 256, 256>>>(recv);
    gemm_n64_kernel<<<gemm_grid, 256>>>(nodes, W_qk, b_qk, qk_p, N_NODES);
    gemm_n64_kernel<<<gemm_grid, 256>>>(nodes, W_v, b_v, v_p, N_NODES);
    edge_attn_kernel<<<(N_NODES + 7) / 8, 256>>>(senders, attn_ptr);
    gemm_n64_kernel<<<gemm_grid, 256>>>(ctx_p, W_out, b_out, out_ptr, N_NODES);
}